// round 15
// baseline (speedup 1.0000x reference)
#include <cuda_runtime.h>
#include <cuda_fp16.h>
#include <math.h>
#include <stdint.h>

// ---------------- problem constants ----------------
#define HDIM   1024
#define NH     16
#define HD     64
#define INTER  2048
#define NE     8
#define SEQ    1024
#define NBATCH 4
#define NTOK   4096
#define TQKV   3072
#define SLOTS  8192

// ---------------- scratch ----------------
__device__ __half g_hn[(size_t)NTOK * HDIM];              // rmsnorm1 out
__device__ __half g_hfh[(size_t)NTOK * HDIM];             // rmsnorm2 out (half)
__device__ __half g_qkvh[(size_t)NTOK * TQKV];            // qkv proj
__device__ __half g_attnh[(size_t)NTOK * HDIM];           // attention out
__device__ __half g_act[(size_t)(SLOTS + 128) * INTER];   // silu(g)*u

__device__ __half g_qkvwt[(size_t)TQKV * HDIM];
__device__ __half g_owt[(size_t)HDIM * HDIM];
__device__ __half g_gupt[(size_t)NE * 2 * INTER * HDIM];
__device__ __half g_dwnt[(size_t)NE * HDIM * INTER];

__device__ int   g_cnt[NE];
__device__ int   g_cur[NE];
__device__ int   g_tok_e[NTOK * 2];
__device__ int   g_slot_tok[SLOTS];
__device__ float g_slot_w[SLOTS];
__device__ float g_tok_w[NTOK * 2];

// ---------------- PTX helpers ----------------
__device__ __forceinline__ uint32_t smem_u32(const void* p) {
    uint32_t a;
    asm("{ .reg .u64 t; cvta.to.shared.u64 t, %1; cvt.u32.u64 %0, t; }" : "=r"(a) : "l"(p));
    return a;
}
#define CP16(dst, src) asm volatile("cp.async.cg.shared.global [%0], [%1], 16;\n" :: "r"(dst), "l"(src) : "memory")
#define CPCOMMIT()     asm volatile("cp.async.commit_group;\n" ::: "memory")
#define CPWAIT(n)      asm volatile("cp.async.wait_group %0;\n" :: "n"(n) : "memory")

__device__ __forceinline__ void ldm4(uint32_t* a, uint32_t addr) {
    asm volatile("ldmatrix.sync.aligned.m8n8.x4.shared.b16 {%0,%1,%2,%3},[%4];"
        : "=r"(a[0]), "=r"(a[1]), "=r"(a[2]), "=r"(a[3]) : "r"(addr));
}
__device__ __forceinline__ void ldm4t(uint32_t* a, uint32_t addr) {
    asm volatile("ldmatrix.sync.aligned.m8n8.x4.trans.shared.b16 {%0,%1,%2,%3},[%4];"
        : "=r"(a[0]), "=r"(a[1]), "=r"(a[2]), "=r"(a[3]) : "r"(addr));
}
__device__ __forceinline__ void mma_f16(float* d, const uint32_t* a, const uint32_t* b) {
    asm volatile("mma.sync.aligned.m16n8k16.row.col.f32.f16.f16.f32 "
                 "{%0,%1,%2,%3},{%4,%5,%6,%7},{%8,%9},{%0,%1,%2,%3};"
        : "+f"(d[0]), "+f"(d[1]), "+f"(d[2]), "+f"(d[3])
        : "r"(a[0]), "r"(a[1]), "r"(a[2]), "r"(a[3]), "r"(b[0]), "r"(b[1]));
}

__device__ __forceinline__ uint32_t swz(uint32_t o) { return o ^ ((o >> 3) & 0x70); }

__device__ __forceinline__ uint32_t pack_h2(float x, float y) {
    __half2 h = __floats2half2_rn(x, y);
    return *(uint32_t*)&h;
}
__device__ __forceinline__ void store_h4(__half* p, float4 v) {
    *(__half2*)p       = __floats2half2_rn(v.x, v.y);
    *(__half2*)(p + 2) = __floats2half2_rn(v.z, v.w);
}

// ---------------- small kernels ----------------
__global__ void rmsnorm_kernel(const float* __restrict__ x, const float* __restrict__ w,
                               __half* __restrict__ yh) {
    int t = blockIdx.x, tid = threadIdx.x;
    if (t == 0 && tid < NE) g_cnt[tid] = 0;   // fused expert-count zeroing
    const float4 v = ((const float4*)(x + (size_t)t * HDIM))[tid];
    float ss = v.x * v.x + v.y * v.y + v.z * v.z + v.w * v.w;
    __shared__ float red[8];
    #pragma unroll
    for (int o = 16; o; o >>= 1) ss += __shfl_xor_sync(0xffffffffu, ss, o);
    if ((tid & 31) == 0) red[tid >> 5] = ss;
    __syncthreads();
    if (tid < 8) {
        float s2 = red[tid];
        #pragma unroll
        for (int o = 4; o; o >>= 1) s2 += __shfl_xor_sync(0xffu, s2, o);
        if (tid == 0) red[0] = s2;
    }
    __syncthreads();
    float inv = rsqrtf(red[0] * (1.0f / HDIM) + 1e-6f);
    const float4 wv = ((const float4*)w)[tid];
    float4 r = make_float4(v.x * inv * wv.x, v.y * inv * wv.y,
                           v.z * inv * wv.z, v.w * inv * wv.w);
    store_h4(yh + (size_t)t * HDIM + tid * 4, r);
}

// rmsnorm2 + router fused; half output; also zeroes g_cur
__global__ void rmsnorm_router_kernel(const float* __restrict__ x, const float* __restrict__ w,
                                      __half* __restrict__ yh, const float* __restrict__ rw) {
    int t = blockIdx.x, tid = threadIdx.x;
    if (t == 0 && tid < NE) g_cur[tid] = 0;
    const float4 v = ((const float4*)(x + (size_t)t * HDIM))[tid];
    float ss = v.x * v.x + v.y * v.y + v.z * v.z + v.w * v.w;
    __shared__ float red[8];
    __shared__ float lg[8][8];
    __shared__ float logits[NE];
    #pragma unroll
    for (int o = 16; o; o >>= 1) ss += __shfl_xor_sync(0xffffffffu, ss, o);
    if ((tid & 31) == 0) red[tid >> 5] = ss;
    __syncthreads();
    if (tid < 8) {
        float s2 = red[tid];
        #pragma unroll
        for (int o = 4; o; o >>= 1) s2 += __shfl_xor_sync(0xffu, s2, o);
        if (tid == 0) red[0] = s2;
    }
    __syncthreads();
    float inv = rsqrtf(red[0] * (1.0f / HDIM) + 1e-6f);
    const float4 wv = ((const float4*)w)[tid];
    float4 r = make_float4(v.x * inv * wv.x, v.y * inv * wv.y,
                           v.z * inv * wv.z, v.w * inv * wv.w);
    store_h4(yh + (size_t)t * HDIM + tid * 4, r);

    float p[NE];
    #pragma unroll
    for (int e = 0; e < NE; e++) p[e] = 0.0f;
    const float* rx = &r.x;
    int i0 = tid * 4;
    #pragma unroll
    for (int q = 0; q < 4; q++) {
        float xv = rx[q];
        const float4* rwp = (const float4*)(rw + (size_t)(i0 + q) * NE);
        float4 w0 = rwp[0], w1 = rwp[1];
        p[0] += xv * w0.x; p[1] += xv * w0.y; p[2] += xv * w0.z; p[3] += xv * w0.w;
        p[4] += xv * w1.x; p[5] += xv * w1.y; p[6] += xv * w1.z; p[7] += xv * w1.w;
    }
    #pragma unroll
    for (int e = 0; e < NE; e++)
        #pragma unroll
        for (int o = 16; o; o >>= 1) p[e] += __shfl_xor_sync(0xffffffffu, p[e], o);
    if ((tid & 31) == 0) {
        int wd = tid >> 5;
        #pragma unroll
        for (int e = 0; e < NE; e++) lg[wd][e] = p[e];
    }
    __syncthreads();
    if (tid < 8) {
        float s = 0.0f;
        #pragma unroll
        for (int wd = 0; wd < 8; wd++) s += lg[wd][tid];
        logits[tid] = s;
    }
    __syncthreads();
    if (tid == 0) {
        int e0 = 0; float b0 = logits[0];
        #pragma unroll
        for (int e = 1; e < NE; e++) if (logits[e] > b0) { b0 = logits[e]; e0 = e; }
        int e1 = -1; float b1 = -3.0e38f;
        #pragma unroll
        for (int e = 0; e < NE; e++)
            if (e != e0 && logits[e] > b1) { b1 = logits[e]; e1 = e; }
        float w0 = 1.0f / (1.0f + expf(b1 - b0));
        g_tok_e[t * 2 + 0] = e0;
        g_tok_e[t * 2 + 1] = e1;
        g_tok_w[t * 2 + 0] = w0;
        g_tok_w[t * 2 + 1] = 1.0f - w0;
        atomicAdd(&g_cnt[e0], 1);
        atomicAdd(&g_cnt[e1], 1);
    }
}

// W[b][K][Nsrc] fp32 -> Wt[b][N][K] half, transposed.
__global__ void wconv_kernel(const float* __restrict__ W, __half* __restrict__ Wt,
                             int K, int N, int ileave, int halfoff) {
    __shared__ float t[64][33];
    int b = blockIdx.z;
    int k0 = blockIdx.y * 64, n0 = blockIdx.x * 32;
    int tx = threadIdx.x & 31, ty = threadIdx.x >> 5;
    const float* Wb = W + (size_t)b * K * N;
    int scol = ileave ? ((n0 >> 1) + (tx >> 1) + (tx & 1) * halfoff) : (n0 + tx);
    #pragma unroll
    for (int q = 0; q < 8; q++) {
        int k = ty + q * 8;
        t[k][tx] = Wb[(size_t)(k0 + k) * N + scol];
    }
    __syncthreads();
    __half* Wtb = Wt + (size_t)b * N * K;
    #pragma unroll
    for (int q = 0; q < 4; q++) {
        int n = ty + q * 8;
        int k = tx * 2;
        *(__half2*)(Wtb + (size_t)(n0 + n) * K + k0 + k) =
            __floats2half2_rn(t[k][n], t[k + 1][n]);
    }
}

// ---------------- fp16 GEMM, 128x128 tile, 256 threads (3-stage) ----------------
#define STAGE_BYTES 32768
#define GST 3
#define GSMEM (GST * STAGE_BYTES + 1024)

// MODE 0: fp32 C (+residual). MODE 1: half out. MODE 2: silu(g)*u half out.
// MODE 3: scatter-combine atomicAdd. IND: A rows resolved through g_slot_tok.
template <int MODE, bool IND>
__device__ __forceinline__ void gemm_f16_core(
    const __half* __restrict__ A, int lda,
    const __half* __restrict__ B, int ldb,
    float* __restrict__ C, int ldc, int Ksrc, int mrem,
    const float* __restrict__ res,
    __half* __restrict__ Ch, int ldch, int slot0)
{
    extern __shared__ __align__(16) char dsm[];
    uint32_t sbase = (smem_u32(dsm) + 1023u) & ~1023u;
    const int tid = threadIdx.x;
    const int wid = tid >> 5, lane = tid & 31;

    const int NC = Ksrc >> 6;
    const int jel = (tid & 7) * 8;
    const int jby = (tid & 7) * 16;
    const int r0 = tid >> 3;

    const int m_warp = (wid & 1) * 64;
    const int n_warp = (wid >> 1) * 32;

    const __half* arow[4];
    #pragma unroll
    for (int q = 0; q < 4; q++) {
        int lr = r0 + q * 32;
        if (IND) {
            int s = slot0 + lr;
            s = (s < SLOTS) ? s : (SLOTS - 1);
            arow[q] = A + (size_t)g_slot_tok[s] * lda + jel;
        } else {
            arow[q] = A + (size_t)lr * lda + jel;
        }
    }
    const __half* brow = B + (size_t)r0 * ldb + jel;

    float acc[4][4][4];
    #pragma unroll
    for (int mt = 0; mt < 4; mt++)
        #pragma unroll
        for (int nt = 0; nt < 4; nt++)
            #pragma unroll
            for (int q = 0; q < 4; q++) acc[mt][nt][q] = 0.0f;

    auto issue = [&](int c) {
        int koff = c * 64;
        uint32_t bA = sbase + (uint32_t)(c % GST) * STAGE_BYTES;
        uint32_t bB = bA + 16384u;
        #pragma unroll
        for (int q = 0; q < 4; q++) {
            uint32_t so = swz((uint32_t)(r0 + q * 32) * 128u + (uint32_t)jby);
            CP16(bA + so, arow[q] + koff);
            CP16(bB + so, brow + (size_t)q * 32 * ldb + koff);
        }
    };

    issue(0); CPCOMMIT();
    issue(1); CPCOMMIT();

    for (int i = 0; i < NC; i++) {
        if (i + 2 < NC) {
            issue(i + 2);
            CPCOMMIT();
            CPWAIT(2);
        } else if (i + 1 < NC) {
            CPWAIT(1);
        } else {
            CPWAIT(0);
        }
        __syncthreads();

        uint32_t aA = sbase + (uint32_t)(i % GST) * STAGE_BYTES;
        uint32_t aB = aA + 16384u;
        #pragma unroll
        for (int ks = 0; ks < 4; ks++) {
            const uint32_t kb = (uint32_t)ks * 32u;
            uint32_t afr[4][4], bfr[2][4];
            #pragma unroll
            for (int mt = 0; mt < 4; mt++)
                ldm4(afr[mt], aA + swz((uint32_t)(m_warp + mt * 16 + (lane & 15)) * 128u
                                       + kb + (uint32_t)(lane >> 4) * 16u));
            #pragma unroll
            for (int ntp = 0; ntp < 2; ntp++)
                ldm4(bfr[ntp], aB + swz((uint32_t)(n_warp + ntp * 16 + ((lane >> 4) & 1) * 8
                                                    + (lane & 7)) * 128u
                                        + kb + (uint32_t)((lane >> 3) & 1) * 16u));
            #pragma unroll
            for (int mt = 0; mt < 4; mt++)
                #pragma unroll
                for (int nt = 0; nt < 4; nt++)
                    mma_f16(acc[mt][nt], afr[mt], &bfr[nt >> 1][(nt & 1) * 2]);
        }
        __syncthreads();
    }

    #pragma unroll
    for (int mt = 0; mt < 4; mt++) {
        int rbase = m_warp + mt * 16 + (lane >> 2);
        #pragma unroll
        for (int half2i = 0; half2i < 2; half2i++) {
            int r = rbase + half2i * 8;
            if (r >= mrem) continue;
            int tok = 0; float wgt = 0.0f;
            if (MODE == 3) {
                int slot = slot0 + r;
                tok = g_slot_tok[slot];
                wgt = g_slot_w[slot];
            }
            #pragma unroll
            for (int nt = 0; nt < 4; nt++) {
                int c = n_warp + nt * 8 + (lane & 3) * 2;
                float2 v = make_float2(acc[mt][nt][half2i * 2], acc[mt][nt][half2i * 2 + 1]);
                if (MODE == 1) {
                    *(__half2*)(Ch + (size_t)r * ldch + c) = __floats2half2_rn(v.x, v.y);
                } else if (MODE == 2) {
                    int j = c >> 1;
                    float g = v.x, u = v.y;
                    float a = g / (1.0f + __expf(-g)) * u;
                    Ch[(size_t)r * ldch + j] = __float2half_rn(a);
                } else if (MODE == 3) {
                    atomicAdd(&C[(size_t)tok * ldc + c],     wgt * v.x);
                    atomicAdd(&C[(size_t)tok * ldc + c + 1], wgt * v.y);
                } else {
                    if (res) {
                        float2 rv = *(const float2*)(res + (size_t)r * ldc + c);
                        v.x += rv.x; v.y += rv.y;
                    }
                    *(float2*)(C + (size_t)r * ldc + c) = v;
                }
            }
        }
    }
}

// qkv GEMM: half out
__global__ void __launch_bounds__(256, 2)
gemm_h16out(const __half* __restrict__ A, int lda,
            const __half* __restrict__ B, int ldb,
            int Ksrc, __half* __restrict__ Ch, int ldch) {
    int bx = blockIdx.x, by = blockIdx.y;
    gemm_f16_core<1, false>(A + (size_t)by * 128 * lda, lda,
                            B + (size_t)bx * 128 * ldb, ldb,
                            nullptr, 0, Ksrc, 128, nullptr,
                            Ch + (size_t)by * 128 * ldch + bx * 128, ldch, 0);
}

// o-proj: fp32 + residual
__global__ void __launch_bounds__(256, 2)
gemm_f32out(const __half* __restrict__ A, int lda,
            const __half* __restrict__ B, int ldb,
            float* __restrict__ C, int ldc, int Ksrc,
            const float* __restrict__ res) {
    int bx = blockIdx.x, by = blockIdx.y;
    gemm_f16_core<0, false>(A + (size_t)by * 128 * lda, lda,
                            B + (size_t)bx * 128 * ldb, ldb,
                            C + (size_t)by * 128 * ldc + bx * 128, ldc, Ksrc, 128,
                            res ? res + (size_t)by * 128 * ldc + bx * 128 : nullptr,
                            nullptr, 0, 0);
}

__device__ __forceinline__ void expert_off_cnt(int e, int& off, int& cnt) {
    off = 0; cnt = 0;
    #pragma unroll
    for (int q = 0; q < NE; q++) {
        int c = g_cnt[q];
        if (q < e) off += c;
        if (q == e) cnt = c;
    }
}

// MoE gate_up with fused silu + fused gather (indirect A rows from hfh)
__global__ void __launch_bounds__(256, 2)
gemm_moe_gu(const __half* __restrict__ Ahf, int lda,
            const __half* __restrict__ Ball, int ldb, long long strideB,
            __half* __restrict__ Ch, int ldch, int Ksrc) {
    int e = blockIdx.z;
    int off, cnt;
    expert_off_cnt(e, off, cnt);
    int by = blockIdx.y, bx = blockIdx.x;
    if (by * 128 >= cnt) return;
    gemm_f16_core<2, true>(Ahf, lda,
                           Ball + (size_t)e * strideB + (size_t)bx * 128 * ldb, ldb,
                           nullptr, 0, Ksrc, cnt - by * 128, nullptr,
                           Ch + (size_t)(off + by * 128) * ldch + bx * 64, ldch,
                           off + by * 128);
}

// MoE down with fused scatter-combine into out (atomicAdd)
__global__ void __launch_bounds__(256, 2)
gemm_moe_dn(const __half* __restrict__ A, int lda,
            const __half* __restrict__ Ball, int ldb, long long strideB,
            float* __restrict__ Out, int ldc, int Ksrc) {
    int e = blockIdx.z;
    int off, cnt;
    expert_off_cnt(e, off, cnt);
    int by = blockIdx.y, bx = blockIdx.x;
    if (by * 128 >= cnt) return;
    gemm_f16_core<3, false>(A + (size_t)(off + by * 128) * lda, lda,
                            Ball + (size_t)e * strideB + (size_t)bx * 128 * ldb, ldb,
                            Out + bx * 128, ldc, Ksrc,
                            cnt - by * 128, nullptr, nullptr, 0, off + by * 128);
}

// ---------------- fp16 tensor-core flash attention (3-stage KV pipeline) ----------------
#define ANT (SEQ / 64)
#define ATTN2_SMEM (16384 + 3 * 16384 + 1024)

__global__ void __launch_bounds__(256, 2)
attn_mma_kernel(const __half* __restrict__ qkvh,
                const float* __restrict__ mask,
                __half* __restrict__ outh) {
    extern __shared__ char asmem[];
    const uint32_t sb = (smem_u32(asmem) + 1023u) & ~1023u;
    const uint32_t QB = sb;
    const int tid = threadIdx.x, lane = tid & 31, wid = tid >> 5;
    const int bh = blockIdx.y, b = bh >> 4, h = bh & 15;
    const int s0 = blockIdx.x * 128;
    const int m_warp = wid * 16;

    const int r0 = tid >> 3;
    const int jel = (tid & 7) * 8;
    const uint32_t jby = (uint32_t)(tid & 7) * 16u;

    {
        const __half* src = qkvh + (size_t)(b * SEQ + s0 + r0) * TQKV + h * HD + jel;
        #pragma unroll
        for (int q = 0; q < 4; q++) {
            uint32_t so = swz((uint32_t)(r0 + q * 32) * 128u + jby);
            CP16(QB + so, src);
            src += (size_t)32 * TQKV;
        }
    }
    auto load_kv = [&](int kt, int st) {
        uint32_t base = sb + 16384u + (uint32_t)st * 16384u;
        const __half* src = qkvh + (size_t)(b * SEQ + kt * 64 + r0) * TQKV
                            + NH * HD + h * HD + jel;
        #pragma unroll
        for (int q = 0; q < 2; q++) {
            uint32_t so = swz((uint32_t)(r0 + q * 32) * 128u + jby);
            CP16(base + so,         src);
            CP16(base + 8192u + so, src + NH * HD);
            src += (size_t)32 * TQKV;
        }
    };
    load_kv(0, 0);
    CPCOMMIT();
    load_kv(1, 1);
    CPCOMMIT();

    float mrow[2] = {-3.0e38f, -3.0e38f}, lrow[2] = {0.0f, 0.0f};
    float o[8][4];
    #pragma unroll
    for (int nt = 0; nt < 8; nt++)
        #pragma unroll
        for (int q = 0; q < 4; q++) o[nt][q] = 0.0f;

    uint32_t qf[4][4];

    for (int kt = 0; kt < ANT; kt++) {
        if (kt + 2 < ANT) {
            load_kv(kt + 2, (kt + 2) % 3);
            CPCOMMIT();
            CPWAIT(2);
        } else if (kt + 1 < ANT) {
            CPWAIT(1);
        } else {
            CPWAIT(0);
        }
        __syncthreads();

        if (kt == 0) {
            #pragma unroll
            for (int ks = 0; ks < 4; ks++) {
                uint32_t ao = swz((uint32_t)(m_warp + (lane & 15)) * 128u
                                  + (uint32_t)ks * 32u + (uint32_t)(lane >> 4) * 16u);
                ldm4(qf[ks], QB + ao);
            }
        }

        const uint32_t KB = sb + 16384u + (uint32_t)(kt % 3) * 16384u;
        const uint32_t VB = KB + 8192u;

        float sv[8][4];
        #pragma unroll
        for (int nt = 0; nt < 8; nt++)
            #pragma unroll
            for (int q = 0; q < 4; q++) sv[nt][q] = 0.0f;

        #pragma unroll
        for (int ks = 0; ks < 4; ks++) {
            uint32_t kh[16];
            #pragma unroll
            for (int np = 0; np < 4; np++) {
                uint32_t ro = swz((uint32_t)(np * 16 + (lane & 7) + ((lane >> 4) << 3)) * 128u
                                  + (uint32_t)ks * 32u + (uint32_t)((lane >> 3) & 1) * 16u);
                ldm4(&kh[np * 4], KB + ro);
            }
            #pragma unroll
            for (int nt = 0; nt < 8; nt++)
                mma_f16(sv[nt], qf[ks], &kh[nt * 2]);
        }

        const float* mbase = mask + (size_t)(s0 + m_warp + (lane >> 2)) * SEQ
                             + kt * 64 + (lane & 3) * 2;
        #pragma unroll
        for (int half2i = 0; half2i < 2; half2i++) {
            const float* mp = mbase + (size_t)half2i * 8 * SEQ;
            float tmax = -3.0e38f;
            #pragma unroll
            for (int nt = 0; nt < 8; nt++) {
                float2 mk = *(const float2*)(mp + nt * 8);
                float a = sv[nt][half2i * 2]     * 0.125f + mk.x;
                float bb = sv[nt][half2i * 2 + 1] * 0.125f + mk.y;
                sv[nt][half2i * 2] = a; sv[nt][half2i * 2 + 1] = bb;
                tmax = fmaxf(tmax, fmaxf(a, bb));
            }
            tmax = fmaxf(tmax, __shfl_xor_sync(0xffffffffu, tmax, 1));
            tmax = fmaxf(tmax, __shfl_xor_sync(0xffffffffu, tmax, 2));
            float mn = fmaxf(mrow[half2i], tmax);
            float corr = __expf(mrow[half2i] - mn);
            float rs = 0.0f;
            #pragma unroll
            for (int nt = 0; nt < 8; nt++) {
                float p0 = __expf(sv[nt][half2i * 2] - mn);
                float p1 = __expf(sv[nt][half2i * 2 + 1] - mn);
                sv[nt][half2i * 2] = p0; sv[nt][half2i * 2 + 1] = p1;
                rs += p0 + p1;
            }
            rs += __shfl_xor_sync(0xffffffffu, rs, 1);
            rs += __shfl_xor_sync(0xffffffffu, rs, 2);
            lrow[half2i] = lrow[half2i] * corr + rs;
            mrow[half2i] = mn;
            #pragma unroll
            for (int nt = 0; nt < 8; nt++) {
                o[nt][half2i * 2] *= corr;
                o[nt][half2i * 2 + 1] *= corr;
            }
        }

        #pragma unroll
        for (int kc = 0; kc < 4; kc++) {
            uint32_t a[4];
            a[0] = pack_h2(sv[2 * kc][0],     sv[2 * kc][1]);
            a[1] = pack_h2(sv[2 * kc][2],     sv[2 * kc][3]);
            a[2] = pack_h2(sv[2 * kc + 1][0], sv[2 * kc + 1][1]);
            a[3] = pack_h2(sv[2 * kc + 1][2], sv[2 * kc + 1][3]);
            uint32_t vh[16];
            #pragma unroll
            for (int np = 0; np < 4; np++) {
                uint32_t ro = swz((uint32_t)(kc * 16 + (lane & 7) + ((lane >> 3) & 1) * 8) * 128u
                                  + (uint32_t)(np * 16 + ((lane >> 4) & 1) * 8) * 2u);
                ldm4t(&vh[np * 4], VB + ro);
            }
            #pragma unroll
            for (int nt = 0; nt < 8; nt++)
                mma_f16(o[nt], a, &vh[nt * 2]);
        }
        __syncthreads();
    }

    float inv0 = 1.0f / lrow[0], inv1 = 1.0f / lrow[1];
    int tok0 = b * SEQ + s0 + m_warp + (lane >> 2);
    int colb = h * HD + (lane & 3) * 2;
    #pragma unroll
    for (int nt = 0; nt < 8; nt++) {
        int c = colb + nt * 8;
        *(__half2*)(outh + (size_t)tok0 * HDIM + c) =
            __floats2half2_rn(o[nt][0] * inv0, o[nt][1] * inv0);
        *(__half2*)(outh + (size_t)(tok0 + 8) * HDIM + c) =
            __floats2half2_rn(o[nt][2] * inv1, o[nt][3] * inv1);
    }
}

// ---------------- routing support ----------------
// slot assignment only; computes expert offsets locally from g_cnt
__global__ void assign_kernel() {
    int t = blockIdx.x * blockDim.x + threadIdx.x;
    if (t >= NTOK) return;
    int offs[NE];
    int acc = 0;
    #pragma unroll
    for (int q = 0; q < NE; q++) { offs[q] = acc; acc += g_cnt[q]; }
    #pragma unroll
    for (int k = 0; k < 2; k++) {
        int e = g_tok_e[t * 2 + k];
        int s = offs[e] + atomicAdd(&g_cur[e], 1);
        g_slot_tok[s] = t;
        g_slot_w[s] = g_tok_w[t * 2 + k];
    }
}

// ---------------- launch ----------------
extern "C" void kernel_launch(void* const* d_in, const int* in_sizes, int n_in,
                              void* d_out, int out_size) {
    const float* hidden = (const float*)d_in[0];
    const float* mask   = (const float*)d_in[1];
    const float* ln1    = (const float*)d_in[2];
    const float* ln2    = (const float*)d_in[3];
    const float* qkv_w  = (const float*)d_in[4];
    const float* o_w    = (const float*)d_in[5];
    const float* rt_w   = (const float*)d_in[6];
    const float* gup    = (const float*)d_in[7];
    const float* dwn    = (const float*)d_in[8];
    float* out = (float*)d_out;

    __half *hn, *hfh, *qkvh, *attnh, *act, *qkvwt, *owt, *gupt, *dwnt;
    cudaGetSymbolAddress((void**)&hn,    g_hn);
    cudaGetSymbolAddress((void**)&hfh,   g_hfh);
    cudaGetSymbolAddress((void**)&qkvh,  g_qkvh);
    cudaGetSymbolAddress((void**)&attnh, g_attnh);
    cudaGetSymbolAddress((void**)&act,   g_act);
    cudaGetSymbolAddress((void**)&qkvwt, g_qkvwt);
    cudaGetSymbolAddress((void**)&owt,   g_owt);
    cudaGetSymbolAddress((void**)&gupt,  g_gupt);
    cudaGetSymbolAddress((void**)&dwnt,  g_dwnt);

    cudaFuncSetAttribute(attn_mma_kernel, cudaFuncAttributeMaxDynamicSharedMemorySize, ATTN2_SMEM);
    cudaFuncSetAttribute(gemm_h16out, cudaFuncAttributeMaxDynamicSharedMemorySize, GSMEM);
    cudaFuncSetAttribute(gemm_f32out, cudaFuncAttributeMaxDynamicSharedMemorySize, GSMEM);
    cudaFuncSetAttribute(gemm_moe_gu, cudaFuncAttributeMaxDynamicSharedMemorySize, GSMEM);
    cudaFuncSetAttribute(gemm_moe_dn, cudaFuncAttributeMaxDynamicSharedMemorySize, GSMEM);

    static cudaStream_t s_side = nullptr;
    static cudaEvent_t ev_fork = nullptr, ev_qkv = nullptr, ev_o = nullptr, ev_join = nullptr;
    if (!s_side) {
        cudaStreamCreateWithFlags(&s_side, cudaStreamNonBlocking);
        cudaEventCreateWithFlags(&ev_fork, cudaEventDisableTiming);
        cudaEventCreateWithFlags(&ev_qkv, cudaEventDisableTiming);
        cudaEventCreateWithFlags(&ev_o, cudaEventDisableTiming);
        cudaEventCreateWithFlags(&ev_join, cudaEventDisableTiming);
    }

    // fork: ALL weight conversions run on the side stream
    cudaEventRecord(ev_fork, 0);
    cudaStreamWaitEvent(s_side, ev_fork, 0);
    wconv_kernel<<<dim3(TQKV / 32, HDIM / 64, 1), 256, 0, s_side>>>(qkv_w, qkvwt, HDIM, TQKV, 0, 0);
    cudaEventRecord(ev_qkv, s_side);
    wconv_kernel<<<dim3(HDIM / 32, HDIM / 64, 1), 256, 0, s_side>>>(o_w, owt, HDIM, HDIM, 0, 0);
    cudaEventRecord(ev_o, s_side);
    wconv_kernel<<<dim3(2 * INTER / 32, HDIM / 64, NE), 256, 0, s_side>>>(
        gup, gupt, HDIM, 2 * INTER, 1, INTER);
    wconv_kernel<<<dim3(HDIM / 32, INTER / 64, NE), 256, 0, s_side>>>(
        dwn, dwnt, INTER, HDIM, 0, 0);
    cudaEventRecord(ev_join, s_side);

    // main stream: rmsnorm1 overlaps qkv wconv
    rmsnorm_kernel<<<NTOK, 256>>>(hidden, ln1, hn);  // also zeroes g_cnt
    cudaStreamWaitEvent(0, ev_qkv, 0);
    gemm_h16out<<<dim3(TQKV / 128, NTOK / 128), 256, GSMEM>>>(
        hn, HDIM, qkvwt, HDIM, HDIM, qkvh, TQKV);
    attn_mma_kernel<<<dim3(SEQ / 128, NBATCH * NH), 256, ATTN2_SMEM>>>(qkvh, mask, attnh);
    cudaStreamWaitEvent(0, ev_o, 0);
    gemm_f32out<<<dim3(HDIM / 128, NTOK / 128), 256, GSMEM>>>(
        attnh, HDIM, owt, HDIM, out, HDIM, HDIM, hidden);

    // moe block (scan eliminated: offsets computed locally from g_cnt)
    rmsnorm_router_kernel<<<NTOK, 256>>>(out, ln2, hfh, rt_w);  // also zeroes g_cur
    assign_kernel<<<NTOK / 256, 256>>>();

    cudaStreamWaitEvent(0, ev_join, 0);

    gemm_moe_gu<<<dim3(2 * INTER / 128, NTOK / 128, NE), 256, GSMEM>>>(
        hfh, HDIM, gupt, HDIM, (long long)(2 * INTER) * HDIM,
        act, INTER, HDIM);
    gemm_moe_dn<<<dim3(HDIM / 128, NTOK / 128, NE), 256, GSMEM>>>(
        act, INTER, dwnt, INTER, (long long)HDIM * INTER,
        out, HDIM, INTER);
}

// round 16
// speedup vs baseline: 1.4537x; 1.4537x over previous
#include <cuda_runtime.h>
#include <cuda_fp16.h>
#include <math.h>
#include <stdint.h>

// ---------------- problem constants ----------------
#define HDIM   1024
#define NH     16
#define HD     64
#define INTER  2048
#define NE     8
#define SEQ    1024
#define NBATCH 4
#define NTOK   4096
#define TQKV   3072
#define SLOTS  8192

// ---------------- scratch ----------------
__device__ __half g_hn[(size_t)NTOK * HDIM];              // rmsnorm1 out
__device__ __half g_hfh[(size_t)NTOK * HDIM];             // rmsnorm2 out (half)
__device__ __half g_qkvh[(size_t)NTOK * TQKV];            // qkv proj
__device__ __half g_attnh[(size_t)NTOK * HDIM];           // attention out
__device__ __half g_act[(size_t)(SLOTS + 128) * INTER];   // silu(g)*u

__device__ __half g_qkvwt[(size_t)TQKV * HDIM];
__device__ __half g_owt[(size_t)HDIM * HDIM];
__device__ __half g_gupt[(size_t)NE * 2 * INTER * HDIM];
__device__ __half g_dwnt[(size_t)NE * HDIM * INTER];

__device__ int   g_cnt[NE];
__device__ int   g_cur[NE];
__device__ int   g_tok_e[NTOK * 2];
__device__ int   g_slot_tok[SLOTS];
__device__ float g_slot_w[SLOTS];
__device__ float g_tok_w[NTOK * 2];

// ---------------- PTX helpers ----------------
__device__ __forceinline__ uint32_t smem_u32(const void* p) {
    uint32_t a;
    asm("{ .reg .u64 t; cvta.to.shared.u64 t, %1; cvt.u32.u64 %0, t; }" : "=r"(a) : "l"(p));
    return a;
}
#define CP16(dst, src) asm volatile("cp.async.cg.shared.global [%0], [%1], 16;\n" :: "r"(dst), "l"(src) : "memory")
#define CPCOMMIT()     asm volatile("cp.async.commit_group;\n" ::: "memory")
#define CPWAIT(n)      asm volatile("cp.async.wait_group %0;\n" :: "n"(n) : "memory")

__device__ __forceinline__ void ldm4(uint32_t* a, uint32_t addr) {
    asm volatile("ldmatrix.sync.aligned.m8n8.x4.shared.b16 {%0,%1,%2,%3},[%4];"
        : "=r"(a[0]), "=r"(a[1]), "=r"(a[2]), "=r"(a[3]) : "r"(addr));
}
__device__ __forceinline__ void ldm4t(uint32_t* a, uint32_t addr) {
    asm volatile("ldmatrix.sync.aligned.m8n8.x4.trans.shared.b16 {%0,%1,%2,%3},[%4];"
        : "=r"(a[0]), "=r"(a[1]), "=r"(a[2]), "=r"(a[3]) : "r"(addr));
}
__device__ __forceinline__ void mma_f16(float* d, const uint32_t* a, const uint32_t* b) {
    asm volatile("mma.sync.aligned.m16n8k16.row.col.f32.f16.f16.f32 "
                 "{%0,%1,%2,%3},{%4,%5,%6,%7},{%8,%9},{%0,%1,%2,%3};"
        : "+f"(d[0]), "+f"(d[1]), "+f"(d[2]), "+f"(d[3])
        : "r"(a[0]), "r"(a[1]), "r"(a[2]), "r"(a[3]), "r"(b[0]), "r"(b[1]));
}

__device__ __forceinline__ uint32_t swz(uint32_t o) { return o ^ ((o >> 3) & 0x70); }

__device__ __forceinline__ uint32_t pack_h2(float x, float y) {
    __half2 h = __floats2half2_rn(x, y);
    return *(uint32_t*)&h;
}
__device__ __forceinline__ void store_h4(__half* p, float4 v) {
    *(__half2*)p       = __floats2half2_rn(v.x, v.y);
    *(__half2*)(p + 2) = __floats2half2_rn(v.z, v.w);
}

// ---------------- small kernels ----------------
__global__ void rmsnorm_kernel(const float* __restrict__ x, const float* __restrict__ w,
                               __half* __restrict__ yh) {
    int t = blockIdx.x, tid = threadIdx.x;
    if (t == 0 && tid < NE) g_cnt[tid] = 0;   // fused expert-count zeroing
    const float4 v = ((const float4*)(x + (size_t)t * HDIM))[tid];
    float ss = v.x * v.x + v.y * v.y + v.z * v.z + v.w * v.w;
    __shared__ float red[8];
    #pragma unroll
    for (int o = 16; o; o >>= 1) ss += __shfl_xor_sync(0xffffffffu, ss, o);
    if ((tid & 31) == 0) red[tid >> 5] = ss;
    __syncthreads();
    if (tid < 8) {
        float s2 = red[tid];
        #pragma unroll
        for (int o = 4; o; o >>= 1) s2 += __shfl_xor_sync(0xffu, s2, o);
        if (tid == 0) red[0] = s2;
    }
    __syncthreads();
    float inv = rsqrtf(red[0] * (1.0f / HDIM) + 1e-6f);
    const float4 wv = ((const float4*)w)[tid];
    float4 r = make_float4(v.x * inv * wv.x, v.y * inv * wv.y,
                           v.z * inv * wv.z, v.w * inv * wv.w);
    store_h4(yh + (size_t)t * HDIM + tid * 4, r);
}

// rmsnorm2 + router fused; half output; also zeroes g_cur
__global__ void rmsnorm_router_kernel(const float* __restrict__ x, const float* __restrict__ w,
                                      __half* __restrict__ yh, const float* __restrict__ rw) {
    int t = blockIdx.x, tid = threadIdx.x;
    if (t == 0 && tid < NE) g_cur[tid] = 0;
    const float4 v = ((const float4*)(x + (size_t)t * HDIM))[tid];
    float ss = v.x * v.x + v.y * v.y + v.z * v.z + v.w * v.w;
    __shared__ float red[8];
    __shared__ float lg[8][8];
    __shared__ float logits[NE];
    #pragma unroll
    for (int o = 16; o; o >>= 1) ss += __shfl_xor_sync(0xffffffffu, ss, o);
    if ((tid & 31) == 0) red[tid >> 5] = ss;
    __syncthreads();
    if (tid < 8) {
        float s2 = red[tid];
        #pragma unroll
        for (int o = 4; o; o >>= 1) s2 += __shfl_xor_sync(0xffu, s2, o);
        if (tid == 0) red[0] = s2;
    }
    __syncthreads();
    float inv = rsqrtf(red[0] * (1.0f / HDIM) + 1e-6f);
    const float4 wv = ((const float4*)w)[tid];
    float4 r = make_float4(v.x * inv * wv.x, v.y * inv * wv.y,
                           v.z * inv * wv.z, v.w * inv * wv.w);
    store_h4(yh + (size_t)t * HDIM + tid * 4, r);

    float p[NE];
    #pragma unroll
    for (int e = 0; e < NE; e++) p[e] = 0.0f;
    const float* rx = &r.x;
    int i0 = tid * 4;
    #pragma unroll
    for (int q = 0; q < 4; q++) {
        float xv = rx[q];
        const float4* rwp = (const float4*)(rw + (size_t)(i0 + q) * NE);
        float4 w0 = rwp[0], w1 = rwp[1];
        p[0] += xv * w0.x; p[1] += xv * w0.y; p[2] += xv * w0.z; p[3] += xv * w0.w;
        p[4] += xv * w1.x; p[5] += xv * w1.y; p[6] += xv * w1.z; p[7] += xv * w1.w;
    }
    #pragma unroll
    for (int e = 0; e < NE; e++)
        #pragma unroll
        for (int o = 16; o; o >>= 1) p[e] += __shfl_xor_sync(0xffffffffu, p[e], o);
    if ((tid & 31) == 0) {
        int wd = tid >> 5;
        #pragma unroll
        for (int e = 0; e < NE; e++) lg[wd][e] = p[e];
    }
    __syncthreads();
    if (tid < 8) {
        float s = 0.0f;
        #pragma unroll
        for (int wd = 0; wd < 8; wd++) s += lg[wd][tid];
        logits[tid] = s;
    }
    __syncthreads();
    if (tid == 0) {
        int e0 = 0; float b0 = logits[0];
        #pragma unroll
        for (int e = 1; e < NE; e++) if (logits[e] > b0) { b0 = logits[e]; e0 = e; }
        int e1 = -1; float b1 = -3.0e38f;
        #pragma unroll
        for (int e = 0; e < NE; e++)
            if (e != e0 && logits[e] > b1) { b1 = logits[e]; e1 = e; }
        float w0 = 1.0f / (1.0f + expf(b1 - b0));
        g_tok_e[t * 2 + 0] = e0;
        g_tok_e[t * 2 + 1] = e1;
        g_tok_w[t * 2 + 0] = w0;
        g_tok_w[t * 2 + 1] = 1.0f - w0;
        atomicAdd(&g_cnt[e0], 1);
        atomicAdd(&g_cnt[e1], 1);
    }
}

// W[b][K][Nsrc] fp32 -> Wt[b][N][K] half, transposed.
__global__ void wconv_kernel(const float* __restrict__ W, __half* __restrict__ Wt,
                             int K, int N, int ileave, int halfoff) {
    __shared__ float t[64][33];
    int b = blockIdx.z;
    int k0 = blockIdx.y * 64, n0 = blockIdx.x * 32;
    int tx = threadIdx.x & 31, ty = threadIdx.x >> 5;
    const float* Wb = W + (size_t)b * K * N;
    int scol = ileave ? ((n0 >> 1) + (tx >> 1) + (tx & 1) * halfoff) : (n0 + tx);
    #pragma unroll
    for (int q = 0; q < 8; q++) {
        int k = ty + q * 8;
        t[k][tx] = Wb[(size_t)(k0 + k) * N + scol];
    }
    __syncthreads();
    __half* Wtb = Wt + (size_t)b * N * K;
    #pragma unroll
    for (int q = 0; q < 4; q++) {
        int n = ty + q * 8;
        int k = tx * 2;
        *(__half2*)(Wtb + (size_t)(n0 + n) * K + k0 + k) =
            __floats2half2_rn(t[k][n], t[k + 1][n]);
    }
}

// ---------------- fp16 GEMM, 128x128 tile, 256 threads (3-stage) ----------------
#define STAGE_BYTES 32768
#define GST 3
#define GSMEM (GST * STAGE_BYTES + 1024)

// MODE 0: fp32 C (+residual). MODE 1: half out. MODE 2: silu(g)*u half out.
// MODE 3: scatter-combine atomicAdd. IND: A rows resolved through g_slot_tok.
template <int MODE, bool IND>
__device__ __forceinline__ void gemm_f16_core(
    const __half* __restrict__ A, int lda,
    const __half* __restrict__ B, int ldb,
    float* __restrict__ C, int ldc, int Ksrc, int mrem,
    const float* __restrict__ res,
    __half* __restrict__ Ch, int ldch, int slot0)
{
    extern __shared__ __align__(16) char dsm[];
    uint32_t sbase = (smem_u32(dsm) + 1023u) & ~1023u;
    const int tid = threadIdx.x;
    const int wid = tid >> 5, lane = tid & 31;

    const int NC = Ksrc >> 6;
    const int jel = (tid & 7) * 8;
    const int jby = (tid & 7) * 16;
    const int r0 = tid >> 3;

    const int m_warp = (wid & 1) * 64;
    const int n_warp = (wid >> 1) * 32;

    const __half* arow[4];
    #pragma unroll
    for (int q = 0; q < 4; q++) {
        int lr = r0 + q * 32;
        if (IND) {
            int s = slot0 + lr;
            s = (s < SLOTS) ? s : (SLOTS - 1);
            arow[q] = A + (size_t)g_slot_tok[s] * lda + jel;
        } else {
            arow[q] = A + (size_t)lr * lda + jel;
        }
    }
    const __half* brow = B + (size_t)r0 * ldb + jel;

    float acc[4][4][4];
    #pragma unroll
    for (int mt = 0; mt < 4; mt++)
        #pragma unroll
        for (int nt = 0; nt < 4; nt++)
            #pragma unroll
            for (int q = 0; q < 4; q++) acc[mt][nt][q] = 0.0f;

    auto issue = [&](int c) {
        int koff = c * 64;
        uint32_t bA = sbase + (uint32_t)(c % GST) * STAGE_BYTES;
        uint32_t bB = bA + 16384u;
        #pragma unroll
        for (int q = 0; q < 4; q++) {
            uint32_t so = swz((uint32_t)(r0 + q * 32) * 128u + (uint32_t)jby);
            CP16(bA + so, arow[q] + koff);
            CP16(bB + so, brow + (size_t)q * 32 * ldb + koff);
        }
    };

    issue(0); CPCOMMIT();
    issue(1); CPCOMMIT();

    for (int i = 0; i < NC; i++) {
        if (i + 2 < NC) {
            issue(i + 2);
            CPCOMMIT();
            CPWAIT(2);
        } else if (i + 1 < NC) {
            CPWAIT(1);
        } else {
            CPWAIT(0);
        }
        __syncthreads();

        uint32_t aA = sbase + (uint32_t)(i % GST) * STAGE_BYTES;
        uint32_t aB = aA + 16384u;
        #pragma unroll
        for (int ks = 0; ks < 4; ks++) {
            const uint32_t kb = (uint32_t)ks * 32u;
            uint32_t afr[4][4], bfr[2][4];
            #pragma unroll
            for (int mt = 0; mt < 4; mt++)
                ldm4(afr[mt], aA + swz((uint32_t)(m_warp + mt * 16 + (lane & 15)) * 128u
                                       + kb + (uint32_t)(lane >> 4) * 16u));
            #pragma unroll
            for (int ntp = 0; ntp < 2; ntp++)
                ldm4(bfr[ntp], aB + swz((uint32_t)(n_warp + ntp * 16 + ((lane >> 4) & 1) * 8
                                                    + (lane & 7)) * 128u
                                        + kb + (uint32_t)((lane >> 3) & 1) * 16u));
            #pragma unroll
            for (int mt = 0; mt < 4; mt++)
                #pragma unroll
                for (int nt = 0; nt < 4; nt++)
                    mma_f16(acc[mt][nt], afr[mt], &bfr[nt >> 1][(nt & 1) * 2]);
        }
        __syncthreads();
    }

    #pragma unroll
    for (int mt = 0; mt < 4; mt++) {
        int rbase = m_warp + mt * 16 + (lane >> 2);
        #pragma unroll
        for (int half2i = 0; half2i < 2; half2i++) {
            int r = rbase + half2i * 8;
            if (r >= mrem) continue;
            int tok = 0; float wgt = 0.0f;
            if (MODE == 3) {
                int slot = slot0 + r;
                tok = g_slot_tok[slot];
                wgt = g_slot_w[slot];
            }
            #pragma unroll
            for (int nt = 0; nt < 4; nt++) {
                int c = n_warp + nt * 8 + (lane & 3) * 2;
                float2 v = make_float2(acc[mt][nt][half2i * 2], acc[mt][nt][half2i * 2 + 1]);
                if (MODE == 1) {
                    *(__half2*)(Ch + (size_t)r * ldch + c) = __floats2half2_rn(v.x, v.y);
                } else if (MODE == 2) {
                    int j = c >> 1;
                    float g = v.x, u = v.y;
                    float a = g / (1.0f + __expf(-g)) * u;
                    Ch[(size_t)r * ldch + j] = __float2half_rn(a);
                } else if (MODE == 3) {
                    atomicAdd(&C[(size_t)tok * ldc + c],     wgt * v.x);
                    atomicAdd(&C[(size_t)tok * ldc + c + 1], wgt * v.y);
                } else {
                    if (res) {
                        float2 rv = *(const float2*)(res + (size_t)r * ldc + c);
                        v.x += rv.x; v.y += rv.y;
                    }
                    *(float2*)(C + (size_t)r * ldc + c) = v;
                }
            }
        }
    }
}

// qkv GEMM: half out
__global__ void __launch_bounds__(256, 2)
gemm_h16out(const __half* __restrict__ A, int lda,
            const __half* __restrict__ B, int ldb,
            int Ksrc, __half* __restrict__ Ch, int ldch) {
    int bx = blockIdx.x, by = blockIdx.y;
    gemm_f16_core<1, false>(A + (size_t)by * 128 * lda, lda,
                            B + (size_t)bx * 128 * ldb, ldb,
                            nullptr, 0, Ksrc, 128, nullptr,
                            Ch + (size_t)by * 128 * ldch + bx * 128, ldch, 0);
}

// o-proj: fp32 + residual
__global__ void __launch_bounds__(256, 2)
gemm_f32out(const __half* __restrict__ A, int lda,
            const __half* __restrict__ B, int ldb,
            float* __restrict__ C, int ldc, int Ksrc,
            const float* __restrict__ res) {
    int bx = blockIdx.x, by = blockIdx.y;
    gemm_f16_core<0, false>(A + (size_t)by * 128 * lda, lda,
                            B + (size_t)bx * 128 * ldb, ldb,
                            C + (size_t)by * 128 * ldc + bx * 128, ldc, Ksrc, 128,
                            res ? res + (size_t)by * 128 * ldc + bx * 128 : nullptr,
                            nullptr, 0, 0);
}

__device__ __forceinline__ void expert_off_cnt(int e, int& off, int& cnt) {
    off = 0; cnt = 0;
    #pragma unroll
    for (int q = 0; q < NE; q++) {
        int c = g_cnt[q];
        if (q < e) off += c;
        if (q == e) cnt = c;
    }
}

// MoE gate_up with fused silu + fused gather (indirect A rows from hfh)
__global__ void __launch_bounds__(256, 2)
gemm_moe_gu(const __half* __restrict__ Ahf, int lda,
            const __half* __restrict__ Ball, int ldb, long long strideB,
            __half* __restrict__ Ch, int ldch, int Ksrc) {
    int e = blockIdx.z;
    int off, cnt;
    expert_off_cnt(e, off, cnt);
    int by = blockIdx.y, bx = blockIdx.x;
    if (by * 128 >= cnt) return;
    gemm_f16_core<2, true>(Ahf, lda,
                           Ball + (size_t)e * strideB + (size_t)bx * 128 * ldb, ldb,
                           nullptr, 0, Ksrc, cnt - by * 128, nullptr,
                           Ch + (size_t)(off + by * 128) * ldch + bx * 64, ldch,
                           off + by * 128);
}

// MoE down with fused scatter-combine into out (atomicAdd)
__global__ void __launch_bounds__(256, 2)
gemm_moe_dn(const __half* __restrict__ A, int lda,
            const __half* __restrict__ Ball, int ldb, long long strideB,
            float* __restrict__ Out, int ldc, int Ksrc) {
    int e = blockIdx.z;
    int off, cnt;
    expert_off_cnt(e, off, cnt);
    int by = blockIdx.y, bx = blockIdx.x;
    if (by * 128 >= cnt) return;
    gemm_f16_core<3, false>(A + (size_t)(off + by * 128) * lda, lda,
                            Ball + (size_t)e * strideB + (size_t)bx * 128 * ldb, ldb,
                            Out + bx * 128, ldc, Ksrc,
                            cnt - by * 128, nullptr, nullptr, 0, off + by * 128);
}

// ---------------- fp16 tensor-core flash attention (3-stage KV pipeline) ----------------
#define ANT (SEQ / 64)
#define ATTN2_SMEM (16384 + 3 * 16384 + 1024)

__global__ void __launch_bounds__(256, 2)
attn_mma_kernel(const __half* __restrict__ qkvh,
                const float* __restrict__ mask,
                __half* __restrict__ outh) {
    extern __shared__ char asmem[];
    const uint32_t sb = (smem_u32(asmem) + 1023u) & ~1023u;
    const uint32_t QB = sb;
    const int tid = threadIdx.x, lane = tid & 31, wid = tid >> 5;
    const int bh = blockIdx.y, b = bh >> 4, h = bh & 15;
    const int s0 = blockIdx.x * 128;
    const int m_warp = wid * 16;

    const int r0 = tid >> 3;
    const int jel = (tid & 7) * 8;
    const uint32_t jby = (uint32_t)(tid & 7) * 16u;

    {
        const __half* src = qkvh + (size_t)(b * SEQ + s0 + r0) * TQKV + h * HD + jel;
        #pragma unroll
        for (int q = 0; q < 4; q++) {
            uint32_t so = swz((uint32_t)(r0 + q * 32) * 128u + jby);
            CP16(QB + so, src);
            src += (size_t)32 * TQKV;
        }
    }
    auto load_kv = [&](int kt, int st) {
        uint32_t base = sb + 16384u + (uint32_t)st * 16384u;
        const __half* src = qkvh + (size_t)(b * SEQ + kt * 64 + r0) * TQKV
                            + NH * HD + h * HD + jel;
        #pragma unroll
        for (int q = 0; q < 2; q++) {
            uint32_t so = swz((uint32_t)(r0 + q * 32) * 128u + jby);
            CP16(base + so,         src);
            CP16(base + 8192u + so, src + NH * HD);
            src += (size_t)32 * TQKV;
        }
    };
    load_kv(0, 0);
    CPCOMMIT();
    load_kv(1, 1);
    CPCOMMIT();

    float mrow[2] = {-3.0e38f, -3.0e38f}, lrow[2] = {0.0f, 0.0f};
    float o[8][4];
    #pragma unroll
    for (int nt = 0; nt < 8; nt++)
        #pragma unroll
        for (int q = 0; q < 4; q++) o[nt][q] = 0.0f;

    uint32_t qf[4][4];

    for (int kt = 0; kt < ANT; kt++) {
        if (kt + 2 < ANT) {
            load_kv(kt + 2, (kt + 2) % 3);
            CPCOMMIT();
            CPWAIT(2);
        } else if (kt + 1 < ANT) {
            CPWAIT(1);
        } else {
            CPWAIT(0);
        }
        __syncthreads();

        if (kt == 0) {
            #pragma unroll
            for (int ks = 0; ks < 4; ks++) {
                uint32_t ao = swz((uint32_t)(m_warp + (lane & 15)) * 128u
                                  + (uint32_t)ks * 32u + (uint32_t)(lane >> 4) * 16u);
                ldm4(qf[ks], QB + ao);
            }
        }

        const uint32_t KB = sb + 16384u + (uint32_t)(kt % 3) * 16384u;
        const uint32_t VB = KB + 8192u;

        float sv[8][4];
        #pragma unroll
        for (int nt = 0; nt < 8; nt++)
            #pragma unroll
            for (int q = 0; q < 4; q++) sv[nt][q] = 0.0f;

        #pragma unroll
        for (int ks = 0; ks < 4; ks++) {
            uint32_t kh[16];
            #pragma unroll
            for (int np = 0; np < 4; np++) {
                uint32_t ro = swz((uint32_t)(np * 16 + (lane & 7) + ((lane >> 4) << 3)) * 128u
                                  + (uint32_t)ks * 32u + (uint32_t)((lane >> 3) & 1) * 16u);
                ldm4(&kh[np * 4], KB + ro);
            }
            #pragma unroll
            for (int nt = 0; nt < 8; nt++)
                mma_f16(sv[nt], qf[ks], &kh[nt * 2]);
        }

        const float* mbase = mask + (size_t)(s0 + m_warp + (lane >> 2)) * SEQ
                             + kt * 64 + (lane & 3) * 2;
        #pragma unroll
        for (int half2i = 0; half2i < 2; half2i++) {
            const float* mp = mbase + (size_t)half2i * 8 * SEQ;
            float tmax = -3.0e38f;
            #pragma unroll
            for (int nt = 0; nt < 8; nt++) {
                float2 mk = *(const float2*)(mp + nt * 8);
                float a = sv[nt][half2i * 2]     * 0.125f + mk.x;
                float bb = sv[nt][half2i * 2 + 1] * 0.125f + mk.y;
                sv[nt][half2i * 2] = a; sv[nt][half2i * 2 + 1] = bb;
                tmax = fmaxf(tmax, fmaxf(a, bb));
            }
            tmax = fmaxf(tmax, __shfl_xor_sync(0xffffffffu, tmax, 1));
            tmax = fmaxf(tmax, __shfl_xor_sync(0xffffffffu, tmax, 2));
            float mn = fmaxf(mrow[half2i], tmax);
            float corr = __expf(mrow[half2i] - mn);
            float rs = 0.0f;
            #pragma unroll
            for (int nt = 0; nt < 8; nt++) {
                float p0 = __expf(sv[nt][half2i * 2] - mn);
                float p1 = __expf(sv[nt][half2i * 2 + 1] - mn);
                sv[nt][half2i * 2] = p0; sv[nt][half2i * 2 + 1] = p1;
                rs += p0 + p1;
            }
            rs += __shfl_xor_sync(0xffffffffu, rs, 1);
            rs += __shfl_xor_sync(0xffffffffu, rs, 2);
            lrow[half2i] = lrow[half2i] * corr + rs;
            mrow[half2i] = mn;
            #pragma unroll
            for (int nt = 0; nt < 8; nt++) {
                o[nt][half2i * 2] *= corr;
                o[nt][half2i * 2 + 1] *= corr;
            }
        }

        #pragma unroll
        for (int kc = 0; kc < 4; kc++) {
            uint32_t a[4];
            a[0] = pack_h2(sv[2 * kc][0],     sv[2 * kc][1]);
            a[1] = pack_h2(sv[2 * kc][2],     sv[2 * kc][3]);
            a[2] = pack_h2(sv[2 * kc + 1][0], sv[2 * kc + 1][1]);
            a[3] = pack_h2(sv[2 * kc + 1][2], sv[2 * kc + 1][3]);
            uint32_t vh[16];
            #pragma unroll
            for (int np = 0; np < 4; np++) {
                uint32_t ro = swz((uint32_t)(kc * 16 + (lane & 7) + ((lane >> 3) & 1) * 8) * 128u
                                  + (uint32_t)(np * 16 + ((lane >> 4) & 1) * 8) * 2u);
                ldm4t(&vh[np * 4], VB + ro);
            }
            #pragma unroll
            for (int nt = 0; nt < 8; nt++)
                mma_f16(o[nt], a, &vh[nt * 2]);
        }
        __syncthreads();
    }

    float inv0 = 1.0f / lrow[0], inv1 = 1.0f / lrow[1];
    int tok0 = b * SEQ + s0 + m_warp + (lane >> 2);
    int colb = h * HD + (lane & 3) * 2;
    #pragma unroll
    for (int nt = 0; nt < 8; nt++) {
        int c = colb + nt * 8;
        *(__half2*)(outh + (size_t)tok0 * HDIM + c) =
            __floats2half2_rn(o[nt][0] * inv0, o[nt][1] * inv0);
        *(__half2*)(outh + (size_t)(tok0 + 8) * HDIM + c) =
            __floats2half2_rn(o[nt][2] * inv1, o[nt][3] * inv1);
    }
}

// ---------------- routing support ----------------
// slot assignment only; computes expert offsets locally from g_cnt
__global__ void assign_kernel() {
    int t = blockIdx.x * blockDim.x + threadIdx.x;
    if (t >= NTOK) return;
    int offs[NE];
    int acc = 0;
    #pragma unroll
    for (int q = 0; q < NE; q++) { offs[q] = acc; acc += g_cnt[q]; }
    #pragma unroll
    for (int k = 0; k < 2; k++) {
        int e = g_tok_e[t * 2 + k];
        int s = offs[e] + atomicAdd(&g_cur[e], 1);
        g_slot_tok[s] = t;
        g_slot_w[s] = g_tok_w[t * 2 + k];
    }
}

// ---------------- launch (R14-proven stream topology) ----------------
extern "C" void kernel_launch(void* const* d_in, const int* in_sizes, int n_in,
                              void* d_out, int out_size) {
    const float* hidden = (const float*)d_in[0];
    const float* mask   = (const float*)d_in[1];
    const float* ln1    = (const float*)d_in[2];
    const float* ln2    = (const float*)d_in[3];
    const float* qkv_w  = (const float*)d_in[4];
    const float* o_w    = (const float*)d_in[5];
    const float* rt_w   = (const float*)d_in[6];
    const float* gup    = (const float*)d_in[7];
    const float* dwn    = (const float*)d_in[8];
    float* out = (float*)d_out;

    __half *hn, *hfh, *qkvh, *attnh, *act, *qkvwt, *owt, *gupt, *dwnt;
    cudaGetSymbolAddress((void**)&hn,    g_hn);
    cudaGetSymbolAddress((void**)&hfh,   g_hfh);
    cudaGetSymbolAddress((void**)&qkvh,  g_qkvh);
    cudaGetSymbolAddress((void**)&attnh, g_attnh);
    cudaGetSymbolAddress((void**)&act,   g_act);
    cudaGetSymbolAddress((void**)&qkvwt, g_qkvwt);
    cudaGetSymbolAddress((void**)&owt,   g_owt);
    cudaGetSymbolAddress((void**)&gupt,  g_gupt);
    cudaGetSymbolAddress((void**)&dwnt,  g_dwnt);

    cudaFuncSetAttribute(attn_mma_kernel, cudaFuncAttributeMaxDynamicSharedMemorySize, ATTN2_SMEM);
    cudaFuncSetAttribute(gemm_h16out, cudaFuncAttributeMaxDynamicSharedMemorySize, GSMEM);
    cudaFuncSetAttribute(gemm_f32out, cudaFuncAttributeMaxDynamicSharedMemorySize, GSMEM);
    cudaFuncSetAttribute(gemm_moe_gu, cudaFuncAttributeMaxDynamicSharedMemorySize, GSMEM);
    cudaFuncSetAttribute(gemm_moe_dn, cudaFuncAttributeMaxDynamicSharedMemorySize, GSMEM);

    static cudaStream_t s_side = nullptr;
    static cudaEvent_t ev_fork = nullptr, ev_o = nullptr, ev_join = nullptr;
    if (!s_side) {
        cudaStreamCreateWithFlags(&s_side, cudaStreamNonBlocking);
        cudaEventCreateWithFlags(&ev_fork, cudaEventDisableTiming);
        cudaEventCreateWithFlags(&ev_o, cudaEventDisableTiming);
        cudaEventCreateWithFlags(&ev_join, cudaEventDisableTiming);
    }

    // fork: o_w + MoE weight conversion overlap the attention block (R14 topology)
    cudaEventRecord(ev_fork, 0);
    cudaStreamWaitEvent(s_side, ev_fork, 0);
    wconv_kernel<<<dim3(HDIM / 32, HDIM / 64, 1), 256, 0, s_side>>>(o_w, owt, HDIM, HDIM, 0, 0);
    cudaEventRecord(ev_o, s_side);
    wconv_kernel<<<dim3(2 * INTER / 32, HDIM / 64, NE), 256, 0, s_side>>>(
        gup, gupt, HDIM, 2 * INTER, 1, INTER);
    wconv_kernel<<<dim3(HDIM / 32, INTER / 64, NE), 256, 0, s_side>>>(
        dwn, dwnt, INTER, HDIM, 0, 0);
    cudaEventRecord(ev_join, s_side);

    // main stream: attention path
    wconv_kernel<<<dim3(TQKV / 32, HDIM / 64, 1), 256>>>(qkv_w, qkvwt, HDIM, TQKV, 0, 0);
    rmsnorm_kernel<<<NTOK, 256>>>(hidden, ln1, hn);  // also zeroes g_cnt
    gemm_h16out<<<dim3(TQKV / 128, NTOK / 128), 256, GSMEM>>>(
        hn, HDIM, qkvwt, HDIM, HDIM, qkvh, TQKV);
    attn_mma_kernel<<<dim3(SEQ / 128, NBATCH * NH), 256, ATTN2_SMEM>>>(qkvh, mask, attnh);
    cudaStreamWaitEvent(0, ev_o, 0);
    gemm_f32out<<<dim3(HDIM / 128, NTOK / 128), 256, GSMEM>>>(
        attnh, HDIM, owt, HDIM, out, HDIM, HDIM, hidden);

    // moe block (scan eliminated: offsets computed locally from g_cnt)
    rmsnorm_router_kernel<<<NTOK, 256>>>(out, ln2, hfh, rt_w);  // also zeroes g_cur
    assign_kernel<<<NTOK / 256, 256>>>();

    cudaStreamWaitEvent(0, ev_join, 0);

    gemm_moe_gu<<<dim3(2 * INTER / 128, NTOK / 128, NE), 256, GSMEM>>>(
        hfh, HDIM, gupt, HDIM, (long long)(2 * INTER) * HDIM,
        act, INTER, HDIM);
    gemm_moe_dn<<<dim3(HDIM / 128, NTOK / 128, NE), 256, GSMEM>>>(
        act, INTER, dwnt, INTER, (long long)HDIM * INTER,
        out, HDIM, INTER);
}

// round 17
// speedup vs baseline: 1.4738x; 1.0138x over previous
#include <cuda_runtime.h>
#include <cuda_fp16.h>
#include <math.h>
#include <stdint.h>

// ---------------- problem constants ----------------
#define HDIM   1024
#define NH     16
#define HD     64
#define INTER  2048
#define NE     8
#define SEQ    1024
#define NBATCH 4
#define NTOK   4096
#define TQKV   3072
#define SLOTS  8192

#define LOG2E 1.4426950408889634f

// ---------------- scratch ----------------
__device__ __half g_hn[(size_t)NTOK * HDIM];              // rmsnorm1 out
__device__ __half g_hfh[(size_t)NTOK * HDIM];             // rmsnorm2 out (half)
__device__ __half g_qkvh[(size_t)NTOK * TQKV];            // qkv proj
__device__ __half g_attnh[(size_t)NTOK * HDIM];           // attention out
__device__ __half g_act[(size_t)(SLOTS + 128) * INTER];   // silu(g)*u
__device__ __half g_maskh[(size_t)SEQ * SEQ];             // mask * log2e, half

__device__ __half g_qkvwt[(size_t)TQKV * HDIM];
__device__ __half g_owt[(size_t)HDIM * HDIM];
__device__ __half g_gupt[(size_t)NE * 2 * INTER * HDIM];
__device__ __half g_dwnt[(size_t)NE * HDIM * INTER];

__device__ int   g_cnt[NE];
__device__ int   g_cur[NE];
__device__ int   g_tok_e[NTOK * 2];
__device__ int   g_slot_tok[SLOTS];
__device__ float g_slot_w[SLOTS];
__device__ float g_tok_w[NTOK * 2];

// ---------------- PTX helpers ----------------
__device__ __forceinline__ uint32_t smem_u32(const void* p) {
    uint32_t a;
    asm("{ .reg .u64 t; cvta.to.shared.u64 t, %1; cvt.u32.u64 %0, t; }" : "=r"(a) : "l"(p));
    return a;
}
#define CP16(dst, src) asm volatile("cp.async.cg.shared.global [%0], [%1], 16;\n" :: "r"(dst), "l"(src) : "memory")
#define CPCOMMIT()     asm volatile("cp.async.commit_group;\n" ::: "memory")
#define CPWAIT(n)      asm volatile("cp.async.wait_group %0;\n" :: "n"(n) : "memory")

__device__ __forceinline__ void ldm4(uint32_t* a, uint32_t addr) {
    asm volatile("ldmatrix.sync.aligned.m8n8.x4.shared.b16 {%0,%1,%2,%3},[%4];"
        : "=r"(a[0]), "=r"(a[1]), "=r"(a[2]), "=r"(a[3]) : "r"(addr));
}
__device__ __forceinline__ void ldm4t(uint32_t* a, uint32_t addr) {
    asm volatile("ldmatrix.sync.aligned.m8n8.x4.trans.shared.b16 {%0,%1,%2,%3},[%4];"
        : "=r"(a[0]), "=r"(a[1]), "=r"(a[2]), "=r"(a[3]) : "r"(addr));
}
__device__ __forceinline__ void mma_f16(float* d, const uint32_t* a, const uint32_t* b) {
    asm volatile("mma.sync.aligned.m16n8k16.row.col.f32.f16.f16.f32 "
                 "{%0,%1,%2,%3},{%4,%5,%6,%7},{%8,%9},{%0,%1,%2,%3};"
        : "+f"(d[0]), "+f"(d[1]), "+f"(d[2]), "+f"(d[3])
        : "r"(a[0]), "r"(a[1]), "r"(a[2]), "r"(a[3]), "r"(b[0]), "r"(b[1]));
}

__device__ __forceinline__ uint32_t swz(uint32_t o) { return o ^ ((o >> 3) & 0x70); }

__device__ __forceinline__ uint32_t pack_h2(float x, float y) {
    __half2 h = __floats2half2_rn(x, y);
    return *(uint32_t*)&h;
}
__device__ __forceinline__ void store_h4(__half* p, float4 v) {
    *(__half2*)p       = __floats2half2_rn(v.x, v.y);
    *(__half2*)(p + 2) = __floats2half2_rn(v.z, v.w);
}

// ---------------- small kernels ----------------
// mask fp32 -> half * log2e (runs once at front of main stream)
__global__ void maskconv_kernel(const float* __restrict__ m) {
    size_t i = ((size_t)blockIdx.x * 256 + threadIdx.x) * 8;
    float4 a = *(const float4*)(m + i);
    float4 b = *(const float4*)(m + i + 4);
    __half* o = g_maskh + i;
    *(__half2*)(o)     = __floats2half2_rn(a.x * LOG2E, a.y * LOG2E);
    *(__half2*)(o + 2) = __floats2half2_rn(a.z * LOG2E, a.w * LOG2E);
    *(__half2*)(o + 4) = __floats2half2_rn(b.x * LOG2E, b.y * LOG2E);
    *(__half2*)(o + 6) = __floats2half2_rn(b.z * LOG2E, b.w * LOG2E);
}

__global__ void rmsnorm_kernel(const float* __restrict__ x, const float* __restrict__ w,
                               __half* __restrict__ yh) {
    int t = blockIdx.x, tid = threadIdx.x;
    if (t == 0 && tid < NE) g_cnt[tid] = 0;
    const float4 v = ((const float4*)(x + (size_t)t * HDIM))[tid];
    float ss = v.x * v.x + v.y * v.y + v.z * v.z + v.w * v.w;
    __shared__ float red[8];
    #pragma unroll
    for (int o = 16; o; o >>= 1) ss += __shfl_xor_sync(0xffffffffu, ss, o);
    if ((tid & 31) == 0) red[tid >> 5] = ss;
    __syncthreads();
    if (tid < 8) {
        float s2 = red[tid];
        #pragma unroll
        for (int o = 4; o; o >>= 1) s2 += __shfl_xor_sync(0xffu, s2, o);
        if (tid == 0) red[0] = s2;
    }
    __syncthreads();
    float inv = rsqrtf(red[0] * (1.0f / HDIM) + 1e-6f);
    const float4 wv = ((const float4*)w)[tid];
    float4 r = make_float4(v.x * inv * wv.x, v.y * inv * wv.y,
                           v.z * inv * wv.z, v.w * inv * wv.w);
    store_h4(yh + (size_t)t * HDIM + tid * 4, r);
}

// rmsnorm2 + router fused; half output; also zeroes g_cur
__global__ void rmsnorm_router_kernel(const float* __restrict__ x, const float* __restrict__ w,
                                      __half* __restrict__ yh, const float* __restrict__ rw) {
    int t = blockIdx.x, tid = threadIdx.x;
    if (t == 0 && tid < NE) g_cur[tid] = 0;
    const float4 v = ((const float4*)(x + (size_t)t * HDIM))[tid];
    float ss = v.x * v.x + v.y * v.y + v.z * v.z + v.w * v.w;
    __shared__ float red[8];
    __shared__ float lg[8][8];
    __shared__ float logits[NE];
    #pragma unroll
    for (int o = 16; o; o >>= 1) ss += __shfl_xor_sync(0xffffffffu, ss, o);
    if ((tid & 31) == 0) red[tid >> 5] = ss;
    __syncthreads();
    if (tid < 8) {
        float s2 = red[tid];
        #pragma unroll
        for (int o = 4; o; o >>= 1) s2 += __shfl_xor_sync(0xffu, s2, o);
        if (tid == 0) red[0] = s2;
    }
    __syncthreads();
    float inv = rsqrtf(red[0] * (1.0f / HDIM) + 1e-6f);
    const float4 wv = ((const float4*)w)[tid];
    float4 r = make_float4(v.x * inv * wv.x, v.y * inv * wv.y,
                           v.z * inv * wv.z, v.w * inv * wv.w);
    store_h4(yh + (size_t)t * HDIM + tid * 4, r);

    float p[NE];
    #pragma unroll
    for (int e = 0; e < NE; e++) p[e] = 0.0f;
    const float* rx = &r.x;
    int i0 = tid * 4;
    #pragma unroll
    for (int q = 0; q < 4; q++) {
        float xv = rx[q];
        const float4* rwp = (const float4*)(rw + (size_t)(i0 + q) * NE);
        float4 w0 = rwp[0], w1 = rwp[1];
        p[0] += xv * w0.x; p[1] += xv * w0.y; p[2] += xv * w0.z; p[3] += xv * w0.w;
        p[4] += xv * w1.x; p[5] += xv * w1.y; p[6] += xv * w1.z; p[7] += xv * w1.w;
    }
    #pragma unroll
    for (int e = 0; e < NE; e++)
        #pragma unroll
        for (int o = 16; o; o >>= 1) p[e] += __shfl_xor_sync(0xffffffffu, p[e], o);
    if ((tid & 31) == 0) {
        int wd = tid >> 5;
        #pragma unroll
        for (int e = 0; e < NE; e++) lg[wd][e] = p[e];
    }
    __syncthreads();
    if (tid < 8) {
        float s = 0.0f;
        #pragma unroll
        for (int wd = 0; wd < 8; wd++) s += lg[wd][tid];
        logits[tid] = s;
    }
    __syncthreads();
    if (tid == 0) {
        int e0 = 0; float b0 = logits[0];
        #pragma unroll
        for (int e = 1; e < NE; e++) if (logits[e] > b0) { b0 = logits[e]; e0 = e; }
        int e1 = -1; float b1 = -3.0e38f;
        #pragma unroll
        for (int e = 0; e < NE; e++)
            if (e != e0 && logits[e] > b1) { b1 = logits[e]; e1 = e; }
        float w0 = 1.0f / (1.0f + expf(b1 - b0));
        g_tok_e[t * 2 + 0] = e0;
        g_tok_e[t * 2 + 1] = e1;
        g_tok_w[t * 2 + 0] = w0;
        g_tok_w[t * 2 + 1] = 1.0f - w0;
        atomicAdd(&g_cnt[e0], 1);
        atomicAdd(&g_cnt[e1], 1);
    }
}

// W[b][K][Nsrc] fp32 -> Wt[b][N][K] half, transposed.
__global__ void wconv_kernel(const float* __restrict__ W, __half* __restrict__ Wt,
                             int K, int N, int ileave, int halfoff) {
    __shared__ float t[64][33];
    int b = blockIdx.z;
    int k0 = blockIdx.y * 64, n0 = blockIdx.x * 32;
    int tx = threadIdx.x & 31, ty = threadIdx.x >> 5;
    const float* Wb = W + (size_t)b * K * N;
    int scol = ileave ? ((n0 >> 1) + (tx >> 1) + (tx & 1) * halfoff) : (n0 + tx);
    #pragma unroll
    for (int q = 0; q < 8; q++) {
        int k = ty + q * 8;
        t[k][tx] = Wb[(size_t)(k0 + k) * N + scol];
    }
    __syncthreads();
    __half* Wtb = Wt + (size_t)b * N * K;
    #pragma unroll
    for (int q = 0; q < 4; q++) {
        int n = ty + q * 8;
        int k = tx * 2;
        *(__half2*)(Wtb + (size_t)(n0 + n) * K + k0 + k) =
            __floats2half2_rn(t[k][n], t[k + 1][n]);
    }
}

// ---------------- fp16 GEMM, 128x128 tile, 256 threads (3-stage) ----------------
#define STAGE_BYTES 32768
#define GST 3
#define GSMEM (GST * STAGE_BYTES + 1024)

// MODE 0: fp32 C (+residual). MODE 1: half out. MODE 2: silu(g)*u half out.
// MODE 3: scatter-combine atomicAdd. IND: A rows resolved through g_slot_tok.
template <int MODE, bool IND>
__device__ __forceinline__ void gemm_f16_core(
    const __half* __restrict__ A, int lda,
    const __half* __restrict__ B, int ldb,
    float* __restrict__ C, int ldc, int Ksrc, int mrem,
    const float* __restrict__ res,
    __half* __restrict__ Ch, int ldch, int slot0)
{
    extern __shared__ __align__(16) char dsm[];
    uint32_t sbase = (smem_u32(dsm) + 1023u) & ~1023u;
    const int tid = threadIdx.x;
    const int wid = tid >> 5, lane = tid & 31;

    const int NC = Ksrc >> 6;
    const int jel = (tid & 7) * 8;
    const int jby = (tid & 7) * 16;
    const int r0 = tid >> 3;

    const int m_warp = (wid & 1) * 64;
    const int n_warp = (wid >> 1) * 32;

    const __half* arow[4];
    #pragma unroll
    for (int q = 0; q < 4; q++) {
        int lr = r0 + q * 32;
        if (IND) {
            int s = slot0 + lr;
            s = (s < SLOTS) ? s : (SLOTS - 1);
            arow[q] = A + (size_t)g_slot_tok[s] * lda + jel;
        } else {
            arow[q] = A + (size_t)lr * lda + jel;
        }
    }
    const __half* brow = B + (size_t)r0 * ldb + jel;

    float acc[4][4][4];
    #pragma unroll
    for (int mt = 0; mt < 4; mt++)
        #pragma unroll
        for (int nt = 0; nt < 4; nt++)
            #pragma unroll
            for (int q = 0; q < 4; q++) acc[mt][nt][q] = 0.0f;

    auto issue = [&](int c) {
        int koff = c * 64;
        uint32_t bA = sbase + (uint32_t)(c % GST) * STAGE_BYTES;
        uint32_t bB = bA + 16384u;
        #pragma unroll
        for (int q = 0; q < 4; q++) {
            uint32_t so = swz((uint32_t)(r0 + q * 32) * 128u + (uint32_t)jby);
            CP16(bA + so, arow[q] + koff);
            CP16(bB + so, brow + (size_t)q * 32 * ldb + koff);
        }
    };

    issue(0); CPCOMMIT();
    issue(1); CPCOMMIT();

    for (int i = 0; i < NC; i++) {
        if (i + 2 < NC) {
            issue(i + 2);
            CPCOMMIT();
            CPWAIT(2);
        } else if (i + 1 < NC) {
            CPWAIT(1);
        } else {
            CPWAIT(0);
        }
        __syncthreads();

        uint32_t aA = sbase + (uint32_t)(i % GST) * STAGE_BYTES;
        uint32_t aB = aA + 16384u;
        #pragma unroll
        for (int ks = 0; ks < 4; ks++) {
            const uint32_t kb = (uint32_t)ks * 32u;
            uint32_t afr[4][4], bfr[2][4];
            #pragma unroll
            for (int mt = 0; mt < 4; mt++)
                ldm4(afr[mt], aA + swz((uint32_t)(m_warp + mt * 16 + (lane & 15)) * 128u
                                       + kb + (uint32_t)(lane >> 4) * 16u));
            #pragma unroll
            for (int ntp = 0; ntp < 2; ntp++)
                ldm4(bfr[ntp], aB + swz((uint32_t)(n_warp + ntp * 16 + ((lane >> 4) & 1) * 8
                                                    + (lane & 7)) * 128u
                                        + kb + (uint32_t)((lane >> 3) & 1) * 16u));
            #pragma unroll
            for (int mt = 0; mt < 4; mt++)
                #pragma unroll
                for (int nt = 0; nt < 4; nt++)
                    mma_f16(acc[mt][nt], afr[mt], &bfr[nt >> 1][(nt & 1) * 2]);
        }
        __syncthreads();
    }

    #pragma unroll
    for (int mt = 0; mt < 4; mt++) {
        int rbase = m_warp + mt * 16 + (lane >> 2);
        #pragma unroll
        for (int half2i = 0; half2i < 2; half2i++) {
            int r = rbase + half2i * 8;
            if (r >= mrem) continue;
            int tok = 0; float wgt = 0.0f;
            if (MODE == 3) {
                int slot = slot0 + r;
                tok = g_slot_tok[slot];
                wgt = g_slot_w[slot];
            }
            #pragma unroll
            for (int nt = 0; nt < 4; nt++) {
                int c = n_warp + nt * 8 + (lane & 3) * 2;
                float2 v = make_float2(acc[mt][nt][half2i * 2], acc[mt][nt][half2i * 2 + 1]);
                if (MODE == 1) {
                    *(__half2*)(Ch + (size_t)r * ldch + c) = __floats2half2_rn(v.x, v.y);
                } else if (MODE == 2) {
                    int j = c >> 1;
                    float g = v.x, u = v.y;
                    float a = g / (1.0f + __expf(-g)) * u;
                    Ch[(size_t)r * ldch + j] = __float2half_rn(a);
                } else if (MODE == 3) {
                    atomicAdd(&C[(size_t)tok * ldc + c],     wgt * v.x);
                    atomicAdd(&C[(size_t)tok * ldc + c + 1], wgt * v.y);
                } else {
                    if (res) {
                        float2 rv = *(const float2*)(res + (size_t)r * ldc + c);
                        v.x += rv.x; v.y += rv.y;
                    }
                    *(float2*)(C + (size_t)r * ldc + c) = v;
                }
            }
        }
    }
}

// qkv GEMM: half out
__global__ void __launch_bounds__(256, 2)
gemm_h16out(const __half* __restrict__ A, int lda,
            const __half* __restrict__ B, int ldb,
            int Ksrc, __half* __restrict__ Ch, int ldch) {
    int bx = blockIdx.x, by = blockIdx.y;
    gemm_f16_core<1, false>(A + (size_t)by * 128 * lda, lda,
                            B + (size_t)bx * 128 * ldb, ldb,
                            nullptr, 0, Ksrc, 128, nullptr,
                            Ch + (size_t)by * 128 * ldch + bx * 128, ldch, 0);
}

// o-proj: fp32 + residual
__global__ void __launch_bounds__(256, 2)
gemm_f32out(const __half* __restrict__ A, int lda,
            const __half* __restrict__ B, int ldb,
            float* __restrict__ C, int ldc, int Ksrc,
            const float* __restrict__ res) {
    int bx = blockIdx.x, by = blockIdx.y;
    gemm_f16_core<0, false>(A + (size_t)by * 128 * lda, lda,
                            B + (size_t)bx * 128 * ldb, ldb,
                            C + (size_t)by * 128 * ldc + bx * 128, ldc, Ksrc, 128,
                            res ? res + (size_t)by * 128 * ldc + bx * 128 : nullptr,
                            nullptr, 0, 0);
}

__device__ __forceinline__ void expert_off_cnt(int e, int& off, int& cnt) {
    off = 0; cnt = 0;
    #pragma unroll
    for (int q = 0; q < NE; q++) {
        int c = g_cnt[q];
        if (q < e) off += c;
        if (q == e) cnt = c;
    }
}

// MoE gate_up with fused silu + fused gather (indirect A rows from hfh)
__global__ void __launch_bounds__(256, 2)
gemm_moe_gu(const __half* __restrict__ Ahf, int lda,
            const __half* __restrict__ Ball, int ldb, long long strideB,
            __half* __restrict__ Ch, int ldch, int Ksrc) {
    int e = blockIdx.z;
    int off, cnt;
    expert_off_cnt(e, off, cnt);
    int by = blockIdx.y, bx = blockIdx.x;
    if (by * 128 >= cnt) return;
    gemm_f16_core<2, true>(Ahf, lda,
                           Ball + (size_t)e * strideB + (size_t)bx * 128 * ldb, ldb,
                           nullptr, 0, Ksrc, cnt - by * 128, nullptr,
                           Ch + (size_t)(off + by * 128) * ldch + bx * 64, ldch,
                           off + by * 128);
}

// MoE down with fused scatter-combine into out (atomicAdd)
__global__ void __launch_bounds__(256, 2)
gemm_moe_dn(const __half* __restrict__ A, int lda,
            const __half* __restrict__ Ball, int ldb, long long strideB,
            float* __restrict__ Out, int ldc, int Ksrc) {
    int e = blockIdx.z;
    int off, cnt;
    expert_off_cnt(e, off, cnt);
    int by = blockIdx.y, bx = blockIdx.x;
    if (by * 128 >= cnt) return;
    gemm_f16_core<3, false>(A + (size_t)(off + by * 128) * lda, lda,
                            Ball + (size_t)e * strideB + (size_t)bx * 128 * ldb, ldb,
                            Out + bx * 128, ldc, Ksrc,
                            cnt - by * 128, nullptr, nullptr, 0, off + by * 128);
}

// ---------------- fp16 tensor-core flash attention (3-stage KV pipeline) ----------------
// softmax in exp2 domain: scores scaled by 0.125*log2e, mask pre-scaled by log2e (half).
#define ANT (SEQ / 64)
#define ATTN2_SMEM (16384 + 3 * 16384 + 1024)
#define QKSCALE (0.125f * LOG2E)

__global__ void __launch_bounds__(256, 2)
attn_mma_kernel(const __half* __restrict__ qkvh,
                __half* __restrict__ outh) {
    extern __shared__ char asmem[];
    const uint32_t sb = (smem_u32(asmem) + 1023u) & ~1023u;
    const uint32_t QB = sb;
    const int tid = threadIdx.x, lane = tid & 31, wid = tid >> 5;
    const int bh = blockIdx.y, b = bh >> 4, h = bh & 15;
    const int s0 = blockIdx.x * 128;
    const int m_warp = wid * 16;

    const int r0 = tid >> 3;
    const int jel = (tid & 7) * 8;
    const uint32_t jby = (uint32_t)(tid & 7) * 16u;

    {
        const __half* src = qkvh + (size_t)(b * SEQ + s0 + r0) * TQKV + h * HD + jel;
        #pragma unroll
        for (int q = 0; q < 4; q++) {
            uint32_t so = swz((uint32_t)(r0 + q * 32) * 128u + jby);
            CP16(QB + so, src);
            src += (size_t)32 * TQKV;
        }
    }
    auto load_kv = [&](int kt, int st) {
        uint32_t base = sb + 16384u + (uint32_t)st * 16384u;
        const __half* src = qkvh + (size_t)(b * SEQ + kt * 64 + r0) * TQKV
                            + NH * HD + h * HD + jel;
        #pragma unroll
        for (int q = 0; q < 2; q++) {
            uint32_t so = swz((uint32_t)(r0 + q * 32) * 128u + jby);
            CP16(base + so,         src);
            CP16(base + 8192u + so, src + NH * HD);
            src += (size_t)32 * TQKV;
        }
    };
    load_kv(0, 0);
    CPCOMMIT();
    load_kv(1, 1);
    CPCOMMIT();

    float mrow[2] = {-3.0e38f, -3.0e38f}, lrow[2] = {0.0f, 0.0f};
    float o[8][4];
    #pragma unroll
    for (int nt = 0; nt < 8; nt++)
        #pragma unroll
        for (int q = 0; q < 4; q++) o[nt][q] = 0.0f;

    uint32_t qf[4][4];

    for (int kt = 0; kt < ANT; kt++) {
        if (kt + 2 < ANT) {
            load_kv(kt + 2, (kt + 2) % 3);
            CPCOMMIT();
            CPWAIT(2);
        } else if (kt + 1 < ANT) {
            CPWAIT(1);
        } else {
            CPWAIT(0);
        }
        __syncthreads();

        if (kt == 0) {
            #pragma unroll
            for (int ks = 0; ks < 4; ks++) {
                uint32_t ao = swz((uint32_t)(m_warp + (lane & 15)) * 128u
                                  + (uint32_t)ks * 32u + (uint32_t)(lane >> 4) * 16u);
                ldm4(qf[ks], QB + ao);
            }
        }

        const uint32_t KB = sb + 16384u + (uint32_t)(kt % 3) * 16384u;
        const uint32_t VB = KB + 8192u;

        float sv[8][4];
        #pragma unroll
        for (int nt = 0; nt < 8; nt++)
            #pragma unroll
            for (int q = 0; q < 4; q++) sv[nt][q] = 0.0f;

        #pragma unroll
        for (int ks = 0; ks < 4; ks++) {
            uint32_t kh[16];
            #pragma unroll
            for (int np = 0; np < 4; np++) {
                uint32_t ro = swz((uint32_t)(np * 16 + (lane & 7) + ((lane >> 4) << 3)) * 128u
                                  + (uint32_t)ks * 32u + (uint32_t)((lane >> 3) & 1) * 16u);
                ldm4(&kh[np * 4], KB + ro);
            }
            #pragma unroll
            for (int nt = 0; nt < 8; nt++)
                mma_f16(sv[nt], qf[ks], &kh[nt * 2]);
        }

        // exp2-domain softmax: scores*QKSCALE + maskh (pre-scaled by log2e)
        const __half* mbase = g_maskh + (size_t)(s0 + m_warp + (lane >> 2)) * SEQ
                              + kt * 64 + (lane & 3) * 2;
        #pragma unroll
        for (int half2i = 0; half2i < 2; half2i++) {
            const __half* mp = mbase + (size_t)half2i * 8 * SEQ;
            float tmax = -3.0e38f;
            #pragma unroll
            for (int nt = 0; nt < 8; nt++) {
                __half2 mh = *(const __half2*)(mp + nt * 8);
                float2 mk = __half22float2(mh);
                float a = fmaf(sv[nt][half2i * 2],     QKSCALE, mk.x);
                float bb = fmaf(sv[nt][half2i * 2 + 1], QKSCALE, mk.y);
                sv[nt][half2i * 2] = a; sv[nt][half2i * 2 + 1] = bb;
                tmax = fmaxf(tmax, fmaxf(a, bb));
            }
            tmax = fmaxf(tmax, __shfl_xor_sync(0xffffffffu, tmax, 1));
            tmax = fmaxf(tmax, __shfl_xor_sync(0xffffffffu, tmax, 2));
            float mn = fmaxf(mrow[half2i], tmax);
            float corr = exp2f(mrow[half2i] - mn);
            float rs = 0.0f;
            #pragma unroll
            for (int nt = 0; nt < 8; nt++) {
                float p0 = exp2f(sv[nt][half2i * 2] - mn);
                float p1 = exp2f(sv[nt][half2i * 2 + 1] - mn);
                sv[nt][half2i * 2] = p0; sv[nt][half2i * 2 + 1] = p1;
                rs += p0 + p1;
            }
            rs += __shfl_xor_sync(0xffffffffu, rs, 1);
            rs += __shfl_xor_sync(0xffffffffu, rs, 2);
            lrow[half2i] = lrow[half2i] * corr + rs;
            mrow[half2i] = mn;
            #pragma unroll
            for (int nt = 0; nt < 8; nt++) {
                o[nt][half2i * 2] *= corr;
                o[nt][half2i * 2 + 1] *= corr;
            }
        }

        #pragma unroll
        for (int kc = 0; kc < 4; kc++) {
            uint32_t a[4];
            a[0] = pack_h2(sv[2 * kc][0],     sv[2 * kc][1]);
            a[1] = pack_h2(sv[2 * kc][2],     sv[2 * kc][3]);
            a[2] = pack_h2(sv[2 * kc + 1][0], sv[2 * kc + 1][1]);
            a[3] = pack_h2(sv[2 * kc + 1][2], sv[2 * kc + 1][3]);
            uint32_t vh[16];
            #pragma unroll
            for (int np = 0; np < 4; np++) {
                uint32_t ro = swz((uint32_t)(kc * 16 + (lane & 7) + ((lane >> 3) & 1) * 8) * 128u
                                  + (uint32_t)(np * 16 + ((lane >> 4) & 1) * 8) * 2u);
                ldm4t(&vh[np * 4], VB + ro);
            }
            #pragma unroll
            for (int nt = 0; nt < 8; nt++)
                mma_f16(o[nt], a, &vh[nt * 2]);
        }
        __syncthreads();
    }

    float inv0 = 1.0f / lrow[0], inv1 = 1.0f / lrow[1];
    int tok0 = b * SEQ + s0 + m_warp + (lane >> 2);
    int colb = h * HD + (lane & 3) * 2;
    #pragma unroll
    for (int nt = 0; nt < 8; nt++) {
        int c = colb + nt * 8;
        *(__half2*)(outh + (size_t)tok0 * HDIM + c) =
            __floats2half2_rn(o[nt][0] * inv0, o[nt][1] * inv0);
        *(__half2*)(outh + (size_t)(tok0 + 8) * HDIM + c) =
            __floats2half2_rn(o[nt][2] * inv1, o[nt][3] * inv1);
    }
}

// ---------------- routing support ----------------
__global__ void assign_kernel() {
    int t = blockIdx.x * blockDim.x + threadIdx.x;
    if (t >= NTOK) return;
    int offs[NE];
    int acc = 0;
    #pragma unroll
    for (int q = 0; q < NE; q++) { offs[q] = acc; acc += g_cnt[q]; }
    #pragma unroll
    for (int k = 0; k < 2; k++) {
        int e = g_tok_e[t * 2 + k];
        int s = offs[e] + atomicAdd(&g_cur[e], 1);
        g_slot_tok[s] = t;
        g_slot_w[s] = g_tok_w[t * 2 + k];
    }
}

// ---------------- launch (R14/R16-proven stream topology) ----------------
extern "C" void kernel_launch(void* const* d_in, const int* in_sizes, int n_in,
                              void* d_out, int out_size) {
    const float* hidden = (const float*)d_in[0];
    const float* mask   = (const float*)d_in[1];
    const float* ln1    = (const float*)d_in[2];
    const float* ln2    = (const float*)d_in[3];
    const float* qkv_w  = (const float*)d_in[4];
    const float* o_w    = (const float*)d_in[5];
    const float* rt_w   = (const float*)d_in[6];
    const float* gup    = (const float*)d_in[7];
    const float* dwn    = (const float*)d_in[8];
    float* out = (float*)d_out;

    __half *hn, *hfh, *qkvh, *attnh, *act, *qkvwt, *owt, *gupt, *dwnt;
    cudaGetSymbolAddress((void**)&hn,    g_hn);
    cudaGetSymbolAddress((void**)&hfh,   g_hfh);
    cudaGetSymbolAddress((void**)&qkvh,  g_qkvh);
    cudaGetSymbolAddress((void**)&attnh, g_attnh);
    cudaGetSymbolAddress((void**)&act,   g_act);
    cudaGetSymbolAddress((void**)&qkvwt, g_qkvwt);
    cudaGetSymbolAddress((void**)&owt,   g_owt);
    cudaGetSymbolAddress((void**)&gupt,  g_gupt);
    cudaGetSymbolAddress((void**)&dwnt,  g_dwnt);

    cudaFuncSetAttribute(attn_mma_kernel, cudaFuncAttributeMaxDynamicSharedMemorySize, ATTN2_SMEM);
    cudaFuncSetAttribute(gemm_h16out, cudaFuncAttributeMaxDynamicSharedMemorySize, GSMEM);
    cudaFuncSetAttribute(gemm_f32out, cudaFuncAttributeMaxDynamicSharedMemorySize, GSMEM);
    cudaFuncSetAttribute(gemm_moe_gu, cudaFuncAttributeMaxDynamicSharedMemorySize, GSMEM);
    cudaFuncSetAttribute(gemm_moe_dn, cudaFuncAttributeMaxDynamicSharedMemorySize, GSMEM);

    static cudaStream_t s_side = nullptr;
    static cudaEvent_t ev_fork = nullptr, ev_o = nullptr, ev_join = nullptr;
    if (!s_side) {
        cudaStreamCreateWithFlags(&s_side, cudaStreamNonBlocking);
        cudaEventCreateWithFlags(&ev_fork, cudaEventDisableTiming);
        cudaEventCreateWithFlags(&ev_o, cudaEventDisableTiming);
        cudaEventCreateWithFlags(&ev_join, cudaEventDisableTiming);
    }

    // fork: o_w + MoE weight conversion overlap the attention block (proven topology)
    cudaEventRecord(ev_fork, 0);
    cudaStreamWaitEvent(s_side, ev_fork, 0);
    wconv_kernel<<<dim3(HDIM / 32, HDIM / 64, 1), 256, 0, s_side>>>(o_w, owt, HDIM, HDIM, 0, 0);
    cudaEventRecord(ev_o, s_side);
    wconv_kernel<<<dim3(2 * INTER / 32, HDIM / 64, NE), 256, 0, s_side>>>(
        gup, gupt, HDIM, 2 * INTER, 1, INTER);
    wconv_kernel<<<dim3(HDIM / 32, INTER / 64, NE), 256, 0, s_side>>>(
        dwn, dwnt, INTER, HDIM, 0, 0);
    cudaEventRecord(ev_join, s_side);

    // main stream: attention path (maskconv first — tiny, feeds attention)
    maskconv_kernel<<<(SEQ * SEQ) / (256 * 8), 256>>>(mask);
    wconv_kernel<<<dim3(TQKV / 32, HDIM / 64, 1), 256>>>(qkv_w, qkvwt, HDIM, TQKV, 0, 0);
    rmsnorm_kernel<<<NTOK, 256>>>(hidden, ln1, hn);  // also zeroes g_cnt
    gemm_h16out<<<dim3(TQKV / 128, NTOK / 128), 256, GSMEM>>>(
        hn, HDIM, qkvwt, HDIM, HDIM, qkvh, TQKV);
    attn_mma_kernel<<<dim3(SEQ / 128, NBATCH * NH), 256, ATTN2_SMEM>>>(qkvh, attnh);
    cudaStreamWaitEvent(0, ev_o, 0);
    gemm_f32out<<<dim3(HDIM / 128, NTOK / 128), 256, GSMEM>>>(
        attnh, HDIM, owt, HDIM, out, HDIM, HDIM, hidden);

    // moe block
    rmsnorm_router_kernel<<<NTOK, 256>>>(out, ln2, hfh, rt_w);  // also zeroes g_cur
    assign_kernel<<<NTOK / 256, 256>>>();

    cudaStreamWaitEvent(0, ev_join, 0);

    gemm_moe_gu<<<dim3(2 * INTER / 128, NTOK / 128, NE), 256, GSMEM>>>(
        hfh, HDIM, gupt, HDIM, (long long)(2 * INTER) * HDIM,
        act, INTER, HDIM);
    gemm_moe_dn<<<dim3(HDIM / 128, NTOK / 128, NE), 256, GSMEM>>>(
        act, INTER, dwnt, INTER, (long long)HDIM * INTER,
        out, HDIM, INTER);
}